// round 1
// baseline (speedup 1.0000x reference)
#include <cuda_runtime.h>

typedef unsigned long long ull;

#define Bn 32
#define Ln 4096
#define Fn 128
#define NLEV 12
#define NSPLIT 16
#define TILE_L 128
#define LTILES (Ln / TILE_L)          // 32
#define TOT (Bn * Ln * Fn)            // 16,777,216
#define GEMM_SMEM (2 * Fn * Fn * 4)   // 131072 bytes

// ---------------- scratch (device globals; no allocation allowed) ----------------
__device__ float g_coef[2][Ln];                 // wavelet coefficients for q,k
__device__ float g_bias[2];                     // wavelet biases
__device__ float g_part[Bn][NSPLIT][2][Fn];     // q/k partial sums
__device__ float g_q[Bn][Fn];
__device__ float g_k[Bn][Fn];
__device__ float g_att[Bn][Fn][Fn];             // softmax(q k^T / sqrt(F))
__device__ float g_Wt[Fn][Fn];                  // ff_w transposed: Wt[f][g] = ff_w[g][f]
__device__ float g_x2[TOT];                     // x + x@att
__device__ float g_y3[TOT];                     // y2 + y2@W^T + ff_b
__device__ float g_stat[Bn][LTILES][2][Fn];     // per-tile sum / sumsq
__device__ float g_sc[Bn][Fn];                  // instance-norm scale
__device__ float g_sh[Bn][Fn];                  // instance-norm shift

// ---------------- packed f32x2 helpers (Blackwell sm_103a) ----------------
__device__ __forceinline__ ull pack2(float lo, float hi) {
    ull r; asm("mov.b64 %0, {%1, %2};" : "=l"(r) : "f"(lo), "f"(hi)); return r;
}
__device__ __forceinline__ ull splat2(float a) {
    ull r; asm("mov.b64 %0, {%1, %1};" : "=l"(r) : "f"(a)); return r;
}
__device__ __forceinline__ ull fma2(ull a, ull b, ull c) {
    ull d; asm("fma.rn.f32x2 %0, %1, %2, %3;" : "=l"(d) : "l"(a), "l"(b), "l"(c)); return d;
}
__device__ __forceinline__ void unpk(ull v, float& lo, float& hi) {
    asm("mov.b64 {%0, %1}, %2;" : "=f"(lo), "=f"(hi) : "l"(v));
}

// ---------------- 1) wavelet coefficients + biases ----------------
__global__ void coef_kernel(const float* __restrict__ qw, const float* __restrict__ qb,
                            const float* __restrict__ kw, const float* __restrict__ kb) {
    int l = blockIdx.x * blockDim.x + threadIdx.x;
    if (l < Ln) {
        float cq = 1.f, ck = 1.f;
        #pragma unroll
        for (int i = 0; i < NLEV; i++) {
            int bit = (l >> i) & 1;
            cq *= qw[2 * i + bit];
            ck *= kw[2 * i + bit];
        }
        g_coef[0][l] = cq;
        g_coef[1][l] = ck;
    }
    if (blockIdx.x == 0 && threadIdx.x == 0) {
        float bq = qb[NLEV - 1], bk = kb[NLEV - 1], pq = 1.f, pk = 1.f;
        for (int i = NLEV - 2; i >= 0; i--) {
            pq *= (qw[2 * (i + 1)] + qw[2 * (i + 1) + 1]);
            pk *= (kw[2 * (i + 1)] + kw[2 * (i + 1) + 1]);
            bq += qb[i] * pq;
            bk += kb[i] * pk;
        }
        g_bias[0] = bq;
        g_bias[1] = bk;
    }
}

// ---------------- 2) q/k weighted reductions over L (partials) ----------------
__global__ void qk_partial(const float* __restrict__ x) {
    const int b = blockIdx.y, ls = blockIdx.x;
    const int tid = threadIdx.x;
    const int f = tid & 127, sub = tid >> 7;
    const int lbase = ls * 256 + sub * 128;
    const float* xp = x + ((size_t)b * Ln + lbase) * Fn + f;
    float aq = 0.f, ak = 0.f;
    #pragma unroll 4
    for (int j = 0; j < 128; j++) {
        float xv = xp[(size_t)j * Fn];
        int l = lbase + j;
        aq = fmaf(g_coef[0][l], xv, aq);
        ak = fmaf(g_coef[1][l], xv, ak);
    }
    __shared__ float sq[256], sk[256];
    sq[tid] = aq; sk[tid] = ak;
    __syncthreads();
    if (tid < 128) {
        g_part[b][ls][0][tid] = sq[tid] + sq[tid + 128];
        g_part[b][ls][1][tid] = sk[tid] + sk[tid + 128];
    }
}

__global__ void qk_reduce() {
    const int b = blockIdx.x, f = threadIdx.x;
    float q = g_bias[0], k = g_bias[1];
    #pragma unroll
    for (int s = 0; s < NSPLIT; s++) {
        q += g_part[b][s][0][f];
        k += g_part[b][s][1][f];
    }
    g_q[b][f] = q;
    g_k[b][f] = k;
}

// ---------------- 3) attention: softmax over rank-1 scores ----------------
__global__ void att_kernel() {
    const int b = blockIdx.y, f = blockIdx.x, g = threadIdx.x;
    const float scale = 0.08838834764831845f;   // 1/sqrt(128)
    float s = g_q[b][f] * g_k[b][g] * scale;
    __shared__ float sm[Fn];
    sm[g] = s;
    __syncthreads();
    for (int o = 64; o > 0; o >>= 1) {
        if (g < o) sm[g] = fmaxf(sm[g], sm[g + o]);
        __syncthreads();
    }
    float mx = sm[0];
    __syncthreads();
    float e = expf(s - mx);
    sm[g] = e;
    __syncthreads();
    for (int o = 64; o > 0; o >>= 1) {
        if (g < o) sm[g] += sm[g + o];
        __syncthreads();
    }
    g_att[b][f][g] = e / sm[0];
}

// ---------------- 4) transpose ff_w once (conflict-free B tiles in GEMM) ----------------
__global__ void transpose_w(const float* __restrict__ ffw) {
    int f = blockIdx.x, g = threadIdx.x;
    g_Wt[f][g] = ffw[g * Fn + f];
}

// ---------------- 5) fused GEMM + residual + per-tile norm stats ----------------
// MODE 0: x2 = x + x @ att[b]            (input = xin param, output = g_x2)
// MODE 1: y3 = y2 + y2 @ Wt + ff_b,  y2 = x2*sc + sh   (input = g_x2, output = g_y3)
template <int MODE>
__global__ __launch_bounds__(256)
void gemm_kernel(const float* __restrict__ xin, const float* __restrict__ ffb) {
    extern __shared__ float smem[];
    float* Bs = smem;              // 128x128 B tile
    float* As = smem + Fn * Fn;    // 128x128 A tile (already affine-transformed for MODE 1)
    const int b = blockIdx.y, lt = blockIdx.x, tid = threadIdx.x;

    const float* Xin  = (MODE == 0) ? xin : g_x2;
    float*       Xout = (MODE == 0) ? g_x2 : g_y3;
    const float* Bsrc = (MODE == 0) ? &g_att[b][0][0] : &g_Wt[0][0];

    // load B tile
    {
        const float4* B4 = (const float4*)Bsrc;
        float4* Bs4 = (float4*)Bs;
        #pragma unroll
        for (int i = tid; i < Fn * Fn / 4; i += 256) Bs4[i] = B4[i];
    }
    // load A tile (+ instance-norm affine for MODE 1)
    const size_t rowbase = (size_t)b * Ln + (size_t)lt * TILE_L;
    {
        const float4* X4 = (const float4*)(Xin + rowbase * Fn);
        float4* As4 = (float4*)As;
        if (MODE == 0) {
            #pragma unroll
            for (int i = tid; i < TILE_L * Fn / 4; i += 256) As4[i] = X4[i];
        } else {
            const float4* sc4 = (const float4*)&g_sc[b][0];
            const float4* sh4 = (const float4*)&g_sh[b][0];
            #pragma unroll
            for (int i = tid; i < TILE_L * Fn / 4; i += 256) {
                float4 v = X4[i];
                int fq = i & 31;
                float4 s = sc4[fq], h = sh4[fq];
                v.x = fmaf(v.x, s.x, h.x); v.y = fmaf(v.y, s.y, h.y);
                v.z = fmaf(v.z, s.z, h.z); v.w = fmaf(v.w, s.w, h.w);
                As4[i] = v;
            }
        }
    }
    __syncthreads();

    const int cg = tid & 15, rg = tid >> 4;
    const int c0 = cg * 4, c1 = 64 + cg * 4, r0 = rg * 8;

    ull acc[8][4];
    #pragma unroll
    for (int i = 0; i < 8; i++)
        #pragma unroll
        for (int j = 0; j < 4; j++) acc[i][j] = 0ull;

    #pragma unroll 4
    for (int k = 0; k < Fn; k++) {
        float4 bA = *(const float4*)&Bs[k * Fn + c0];
        float4 bB = *(const float4*)&Bs[k * Fn + c1];
        ull b0 = pack2(bA.x, bA.y), b1 = pack2(bA.z, bA.w);
        ull b2 = pack2(bB.x, bB.y), b3 = pack2(bB.z, bB.w);
        #pragma unroll
        for (int i = 0; i < 8; i++) {
            ull a = splat2(As[(r0 + i) * Fn + k]);
            acc[i][0] = fma2(a, b0, acc[i][0]);
            acc[i][1] = fma2(a, b1, acc[i][1]);
            acc[i][2] = fma2(a, b2, acc[i][2]);
            acc[i][3] = fma2(a, b3, acc[i][3]);
        }
    }

    float fb[8];
    #pragma unroll
    for (int j = 0; j < 4; j++) {
        fb[j]     = (MODE == 1) ? ffb[c0 + j] : 0.f;
        fb[4 + j] = (MODE == 1) ? ffb[c1 + j] : 0.f;
    }

    float cs[8], cq[8];
    #pragma unroll
    for (int j = 0; j < 8; j++) { cs[j] = 0.f; cq[j] = 0.f; }

    #pragma unroll
    for (int i = 0; i < 8; i++) {
        int l = r0 + i;
        float4 ra = *(const float4*)&As[l * Fn + c0];   // residual (x or y2)
        float4 rb = *(const float4*)&As[l * Fn + c1];
        float v[8], lo, hi;
        unpk(acc[i][0], lo, hi); v[0] = ra.x + lo + fb[0]; v[1] = ra.y + hi + fb[1];
        unpk(acc[i][1], lo, hi); v[2] = ra.z + lo + fb[2]; v[3] = ra.w + hi + fb[3];
        unpk(acc[i][2], lo, hi); v[4] = rb.x + lo + fb[4]; v[5] = rb.y + hi + fb[5];
        unpk(acc[i][3], lo, hi); v[6] = rb.z + lo + fb[6]; v[7] = rb.w + hi + fb[7];
        float* op = Xout + (rowbase + l) * Fn;
        *(float4*)(op + c0) = make_float4(v[0], v[1], v[2], v[3]);
        *(float4*)(op + c1) = make_float4(v[4], v[5], v[6], v[7]);
        #pragma unroll
        for (int j = 0; j < 8; j++) { cs[j] += v[j]; cq[j] = fmaf(v[j], v[j], cq[j]); }
    }

    // block reduction of per-column sum/sumsq into g_stat[b][lt]
    __syncthreads();
    float* red_s = smem;             // 16 x 128
    float* red_q = smem + 16 * Fn;   // 16 x 128
    #pragma unroll
    for (int j = 0; j < 4; j++) {
        red_s[rg * Fn + c0 + j] = cs[j];     red_s[rg * Fn + c1 + j] = cs[4 + j];
        red_q[rg * Fn + c0 + j] = cq[j];     red_q[rg * Fn + c1 + j] = cq[4 + j];
    }
    __syncthreads();
    if (tid < Fn) {
        float s = 0.f, q = 0.f;
        #pragma unroll
        for (int r = 0; r < 16; r++) { s += red_s[r * Fn + tid]; q += red_q[r * Fn + tid]; }
        g_stat[b][lt][0][tid] = s;
        g_stat[b][lt][1][tid] = q;
    }
}

// ---------------- 6) finalize instance-norm stats -> scale/shift ----------------
__global__ void stat_reduce(const float* __restrict__ gamma, const float* __restrict__ beta) {
    const int b = blockIdx.x, g = threadIdx.x;
    float s = 0.f, q = 0.f;
    #pragma unroll
    for (int t = 0; t < LTILES; t++) {
        s += g_stat[b][t][0][g];
        q += g_stat[b][t][1][g];
    }
    const float inv = 1.f / (float)Ln;
    float m = s * inv;
    float v = q * inv - m * m;
    float rs = rsqrtf(v + 1e-5f);
    float sc = rs * gamma[g];
    g_sc[b][g] = sc;
    g_sh[b][g] = fmaf(-m, sc, beta[g]);
}

// ---------------- 7) final normalize: out = y3*sc2 + sh2 ----------------
__global__ void final_kernel(float* __restrict__ out) {
    int i = blockIdx.x * blockDim.x + threadIdx.x;   // float4 index
    int b = i >> 17;                                  // 4096*128/4 = 2^17 float4 per batch
    int fq = i & 31;
    float4 v = ((const float4*)g_y3)[i];
    float4 s = ((const float4*)&g_sc[b][0])[fq];
    float4 h = ((const float4*)&g_sh[b][0])[fq];
    v.x = fmaf(v.x, s.x, h.x); v.y = fmaf(v.y, s.y, h.y);
    v.z = fmaf(v.z, s.z, h.z); v.w = fmaf(v.w, s.w, h.w);
    ((float4*)out)[i] = v;
}

// ---------------- launch ----------------
extern "C" void kernel_launch(void* const* d_in, const int* in_sizes, int n_in,
                              void* d_out, int out_size) {
    const float* x     = (const float*)d_in[0];
    const float* qw    = (const float*)d_in[1];
    const float* qb    = (const float*)d_in[2];
    const float* kw    = (const float*)d_in[3];
    const float* kb    = (const float*)d_in[4];
    const float* ffw   = (const float*)d_in[5];
    const float* ffb   = (const float*)d_in[6];
    const float* gamma = (const float*)d_in[7];
    const float* beta  = (const float*)d_in[8];
    float* out = (float*)d_out;

    cudaFuncSetAttribute((const void*)gemm_kernel<0>,
                         cudaFuncAttributeMaxDynamicSharedMemorySize, GEMM_SMEM);
    cudaFuncSetAttribute((const void*)gemm_kernel<1>,
                         cudaFuncAttributeMaxDynamicSharedMemorySize, GEMM_SMEM);

    coef_kernel<<<(Ln + 255) / 256, 256>>>(qw, qb, kw, kb);
    qk_partial<<<dim3(NSPLIT, Bn), 256>>>(x);
    qk_reduce<<<Bn, Fn>>>();
    att_kernel<<<dim3(Fn, Bn), Fn>>>();
    transpose_w<<<Fn, Fn>>>(ffw);

    gemm_kernel<0><<<dim3(LTILES, Bn), 256, GEMM_SMEM>>>(x, ffb);
    stat_reduce<<<Bn, Fn>>>(gamma, beta);
    gemm_kernel<1><<<dim3(LTILES, Bn), 256, GEMM_SMEM>>>(x, ffb);
    stat_reduce<<<Bn, Fn>>>(gamma, beta);
    final_kernel<<<TOT / 4 / 256, 256>>>(out);
}

// round 3
// speedup vs baseline: 1.0547x; 1.0547x over previous
#include <cuda_runtime.h>
#include <cuda_bf16.h>
#include <cstdint>

#define Bn 32
#define Ln 4096
#define Fn 128
#define NLEV 12
#define NSPLIT 16
#define TILE_L 128
#define LTILES (Ln / TILE_L)            // 32
#define TOT (Bn * Ln * Fn)
#define TILES_PER_CTA 8
#define GRIDX (LTILES / TILES_PER_CTA)  // 4

// smem byte offsets (GEMM kernel). bf16 tiles use 136-element row stride.
#define SM_AH 0
#define SM_AL 34816
#define SM_BH 69632
#define SM_BL 104448
#define SM_CS 139264                    // float staging 128 x 132
#define GEMM_SMEM (139264 + 128 * 132 * 4)   // 206848

// ---------------- scratch ----------------
__device__ float g_coef[2][Ln];
__device__ float g_bias[2];
__device__ float g_part[Bn][NSPLIT][2][Fn];
__device__ float g_q[Bn][Fn];
__device__ float g_k[Bn][Fn];
__device__ float g_att[Bn][Fn][Fn];
__device__ float g_x2[TOT];
__device__ float g_y3[TOT];
__device__ float g_stat[Bn][GRIDX][2][Fn];
__device__ float g_sc[Bn][Fn];
__device__ float g_sh[Bn][Fn];
// pre-split B operands, plain row-major Bt[n][k]: [0..31] att^T per batch, [32] ff_w
__device__ __nv_bfloat16 g_B0[Bn + 1][Fn * Fn];
__device__ __nv_bfloat16 g_B1[Bn + 1][Fn * Fn];

__device__ __forceinline__ uint32_t smem_u32(const void* p) {
    uint32_t a;
    asm("{ .reg .u64 t; cvta.to.shared.u64 t, %1; cvt.u32.u64 %0, t; }" : "=r"(a) : "l"(p));
    return a;
}

#define LDSM4(r0, r1, r2, r3, addr) \
    asm volatile("ldmatrix.sync.aligned.m8n8.x4.shared.b16 {%0,%1,%2,%3}, [%4];" \
                 : "=r"(r0), "=r"(r1), "=r"(r2), "=r"(r3) : "r"(addr))

#define MMA16816(c0, c1, c2, c3, a0, a1, a2, a3, b0, b1) \
    asm volatile("mma.sync.aligned.m16n8k16.row.col.f32.bf16.bf16.f32 " \
                 "{%0,%1,%2,%3}, {%4,%5,%6,%7}, {%8,%9}, {%0,%1,%2,%3};" \
                 : "+f"(c0), "+f"(c1), "+f"(c2), "+f"(c3) \
                 : "r"(a0), "r"(a1), "r"(a2), "r"(a3), "r"(b0), "r"(b1))

// ---------------- 1) wavelet coefficients + biases ----------------
__global__ void coef_kernel(const float* __restrict__ qw, const float* __restrict__ qb,
                            const float* __restrict__ kw, const float* __restrict__ kb) {
    int l = blockIdx.x * blockDim.x + threadIdx.x;
    if (l < Ln) {
        float cq = 1.f, ck = 1.f;
        #pragma unroll
        for (int i = 0; i < NLEV; i++) {
            int bit = (l >> i) & 1;
            cq *= qw[2 * i + bit];
            ck *= kw[2 * i + bit];
        }
        g_coef[0][l] = cq;
        g_coef[1][l] = ck;
    }
    if (blockIdx.x == 0 && threadIdx.x == 0) {
        float bq = qb[NLEV - 1], bk = kb[NLEV - 1], pq = 1.f, pk = 1.f;
        for (int i = NLEV - 2; i >= 0; i--) {
            pq *= (qw[2 * (i + 1)] + qw[2 * (i + 1) + 1]);
            pk *= (kw[2 * (i + 1)] + kw[2 * (i + 1) + 1]);
            bq += qb[i] * pq;
            bk += kb[i] * pk;
        }
        g_bias[0] = bq;
        g_bias[1] = bk;
    }
}

// ---------------- 2) q/k reductions ----------------
__global__ void qk_partial(const float* __restrict__ x) {
    const int b = blockIdx.y, ls = blockIdx.x;
    const int tid = threadIdx.x;
    const int f = tid & 127, sub = tid >> 7;
    const int lbase = ls * 256 + sub * 128;
    const float* xp = x + ((size_t)b * Ln + lbase) * Fn + f;
    float aq = 0.f, ak = 0.f;
    #pragma unroll 4
    for (int j = 0; j < 128; j++) {
        float xv = xp[(size_t)j * Fn];
        int l = lbase + j;
        aq = fmaf(g_coef[0][l], xv, aq);
        ak = fmaf(g_coef[1][l], xv, ak);
    }
    __shared__ float sq[256], sk[256];
    sq[tid] = aq; sk[tid] = ak;
    __syncthreads();
    if (tid < 128) {
        g_part[b][ls][0][tid] = sq[tid] + sq[tid + 128];
        g_part[b][ls][1][tid] = sk[tid] + sk[tid + 128];
    }
}

__global__ void qk_reduce() {
    const int b = blockIdx.x, f = threadIdx.x;
    float q = g_bias[0], k = g_bias[1];
    #pragma unroll
    for (int s = 0; s < NSPLIT; s++) {
        q += g_part[b][s][0][f];
        k += g_part[b][s][1][f];
    }
    g_q[b][f] = q;
    g_k[b][f] = k;
}

// ---------------- 3) attention softmax ----------------
__global__ void att_kernel() {
    const int b = blockIdx.y, f = blockIdx.x, g = threadIdx.x;
    const float scale = 0.08838834764831845f;
    float s = g_q[b][f] * g_k[b][g] * scale;
    __shared__ float sm[Fn];
    sm[g] = s;
    __syncthreads();
    for (int o = 64; o > 0; o >>= 1) {
        if (g < o) sm[g] = fmaxf(sm[g], sm[g + o]);
        __syncthreads();
    }
    float mx = sm[0];
    __syncthreads();
    float e = expf(s - mx);
    sm[g] = e;
    __syncthreads();
    for (int o = 64; o > 0; o >>= 1) {
        if (g < o) sm[g] += sm[g + o];
        __syncthreads();
    }
    g_att[b][f][g] = e / sm[0];
}

// ---------------- 4) pre-split B operands (plain row-major Bt[n][k]) ----------------
__global__ void prep_B(const float* __restrict__ ffw) {
    int b = blockIdx.x;
    for (int idx = threadIdx.x; idx < Fn * Fn; idx += blockDim.x) {
        int n = idx >> 7, k = idx & 127;
        float v = (b < Bn) ? g_att[b][k][n] : ffw[n * Fn + k];
        __nv_bfloat16 h0 = __float2bfloat16(v);
        __nv_bfloat16 h1 = __float2bfloat16(v - __bfloat162float(h0));
        g_B0[b][idx] = h0;
        g_B1[b][idx] = h1;
    }
}

// ---------------- 5) mma.sync GEMM + residual (+bias) + fused norm stats ----------------
// MODE 0: x2 = x + x @ att          MODE 1: y3 = y2 + y2 @ ff_w^T + ffb, y2 = x2*sc+sh
template <int MODE>
__global__ __launch_bounds__(256, 1)
void mma_gemm(const float* __restrict__ xin, const float* __restrict__ ffb) {
    extern __shared__ char smem[];
    const uint32_t sbase = smem_u32(smem);
    const int tid = threadIdx.x, lane = tid & 31, w = tid >> 5;
    const int wm = w & 3, wn = w >> 2;
    const int b = blockIdx.y;

    // ---- load pre-split B tiles into smem (restriding 128 -> 136 bf16) ----
    {
        const int bb = (MODE == 0) ? b : Bn;
        const uint4* s0 = (const uint4*)&g_B0[bb][0];
        const uint4* s1 = (const uint4*)&g_B1[bb][0];
        #pragma unroll
        for (int i = tid; i < 2048; i += 256) {
            int row = i >> 4, kc = i & 15;
            uint32_t off = (uint32_t)row * 272 + (uint32_t)kc * 16;
            *(uint4*)(smem + SM_BH + off) = s0[i];
            *(uint4*)(smem + SM_BL + off) = s1[i];
        }
    }

    // ---- per-thread ldmatrix address bases (byte offsets, k added per step) ----
    const uint32_t aoff0 = ((uint32_t)(wm * 32 + (lane & 15)) * 136 + ((lane >> 4) << 3)) * 2;
    const uint32_t aoff1 = aoff0 + 16 * 136 * 2;
    uint32_t boff[4];
    #pragma unroll
    for (int q = 0; q < 4; q++)
        boff[q] = ((uint32_t)(wn * 64 + q * 16 + (lane & 7) + ((lane & 16) >> 1)) * 136 +
                   (((lane >> 3) & 1) << 3)) * 2;

    // per-thread affine params for conversion/residual (c4 fixed = (tid&31)*4)
    float4 s4 = make_float4(1.f, 1.f, 1.f, 1.f), h4 = make_float4(0.f, 0.f, 0.f, 0.f);
    float4 fb4 = make_float4(0.f, 0.f, 0.f, 0.f);
    if (MODE == 1) {
        s4 = ((const float4*)&g_sc[b][0])[tid & 31];
        h4 = ((const float4*)&g_sh[b][0])[tid & 31];
        fb4 = ((const float4*)ffb)[tid & 31];
    }

    float run_s[4] = {0.f, 0.f, 0.f, 0.f}, run_q[4] = {0.f, 0.f, 0.f, 0.f};

    for (int t = 0; t < TILES_PER_CTA; t++) {
        const int lt = blockIdx.x * TILES_PER_CTA + t;
        const size_t rowbase = (size_t)b * Ln + (size_t)lt * TILE_L;
        const float4* X4 = (const float4*)((MODE == 0 ? xin : g_x2) + rowbase * Fn);
        float4* Y4 = (float4*)((MODE == 0 ? g_x2 : g_y3) + rowbase * Fn);

        // ---- convert A tile: fp32 -> bf16 hi/lo, stride 136 ----
        #pragma unroll
        for (int i = tid; i < 4096; i += 256) {
            int r = i >> 5, c4 = (i & 31) << 2;
            float4 v = X4[i];
            if (MODE == 1) {
                v.x = fmaf(v.x, s4.x, h4.x); v.y = fmaf(v.y, s4.y, h4.y);
                v.z = fmaf(v.z, s4.z, h4.z); v.w = fmaf(v.w, s4.w, h4.w);
            }
            __nv_bfloat162 p0h, p1h, p0l, p1l;
            p0h.x = __float2bfloat16(v.x); p0h.y = __float2bfloat16(v.y);
            p1h.x = __float2bfloat16(v.z); p1h.y = __float2bfloat16(v.w);
            p0l.x = __float2bfloat16(v.x - __bfloat162float(p0h.x));
            p0l.y = __float2bfloat16(v.y - __bfloat162float(p0h.y));
            p1l.x = __float2bfloat16(v.z - __bfloat162float(p1h.x));
            p1l.y = __float2bfloat16(v.w - __bfloat162float(p1h.y));
            uint32_t off = ((uint32_t)r * 136 + (uint32_t)c4) * 2;
            *(__nv_bfloat162*)(smem + SM_AH + off)     = p0h;
            *(__nv_bfloat162*)(smem + SM_AH + off + 4) = p1h;
            *(__nv_bfloat162*)(smem + SM_AL + off)     = p0l;
            *(__nv_bfloat162*)(smem + SM_AL + off + 4) = p1l;
        }
        __syncthreads();

        // ---- mma: 3 splits x 8 k-steps x 16 HMMA ----
        float c[2][8][4];
        #pragma unroll
        for (int mi = 0; mi < 2; mi++)
            #pragma unroll
            for (int ni = 0; ni < 8; ni++)
                #pragma unroll
                for (int j = 0; j < 4; j++) c[mi][ni][j] = 0.f;

        #pragma unroll
        for (int s = 0; s < 3; s++) {
            const uint32_t Ab = sbase + (s == 1 ? SM_AL : SM_AH);
            const uint32_t Bb = sbase + (s == 2 ? SM_BL : SM_BH);
            #pragma unroll
            for (int kb = 0; kb < 8; kb++) {
                const uint32_t kbyte = (uint32_t)kb << 5;
                uint32_t a[2][4], bq[4][4];
                LDSM4(a[0][0], a[0][1], a[0][2], a[0][3], Ab + aoff0 + kbyte);
                LDSM4(a[1][0], a[1][1], a[1][2], a[1][3], Ab + aoff1 + kbyte);
                #pragma unroll
                for (int q = 0; q < 4; q++)
                    LDSM4(bq[q][0], bq[q][1], bq[q][2], bq[q][3], Bb + boff[q] + kbyte);
                #pragma unroll
                for (int mi = 0; mi < 2; mi++)
                    #pragma unroll
                    for (int ni = 0; ni < 8; ni++) {
                        const int q = ni >> 1, r2 = (ni & 1) << 1;
                        MMA16816(c[mi][ni][0], c[mi][ni][1], c[mi][ni][2], c[mi][ni][3],
                                 a[mi][0], a[mi][1], a[mi][2], a[mi][3],
                                 bq[q][r2], bq[q][r2 + 1]);
                    }
            }
        }
        __syncthreads();   // all ldmatrix reads done before staging reuses nothing, but A rewrite next tile

        // ---- stage C to smem (float, stride 132) ----
        {
            const int row0 = wm * 32 + (lane >> 2);
            const int colb = wn * 64 + ((lane & 3) << 1);
            #pragma unroll
            for (int mi = 0; mi < 2; mi++)
                #pragma unroll
                for (int ni = 0; ni < 8; ni++) {
                    const int r = row0 + mi * 16, cc = colb + ni * 8;
                    float* p0 = (float*)(smem + SM_CS) + r * 132 + cc;
                    p0[0] = c[mi][ni][0];
                    p0[1] = c[mi][ni][1];
                    float* p1 = p0 + 8 * 132;
                    p1[0] = c[mi][ni][2];
                    p1[1] = c[mi][ni][3];
                }
        }
        __syncthreads();

        // ---- residual + bias + write + column stats ----
        float cs[4] = {0.f, 0.f, 0.f, 0.f}, cq[4] = {0.f, 0.f, 0.f, 0.f};
        #pragma unroll
        for (int j = 0; j < 16; j++) {
            int i = tid + 256 * j;
            int r = i >> 5, cg = i & 31;
            float4 v = ((const float4*)(smem + SM_CS))[r * 33 + cg];
            float4 xr = X4[i];
            if (MODE == 1) {
                xr.x = fmaf(xr.x, s4.x, h4.x); xr.y = fmaf(xr.y, s4.y, h4.y);
                xr.z = fmaf(xr.z, s4.z, h4.z); xr.w = fmaf(xr.w, s4.w, h4.w);
            }
            v.x += xr.x + fb4.x; v.y += xr.y + fb4.y;
            v.z += xr.z + fb4.z; v.w += xr.w + fb4.w;
            Y4[i] = v;
            cs[0] += v.x; cs[1] += v.y; cs[2] += v.z; cs[3] += v.w;
            cq[0] = fmaf(v.x, v.x, cq[0]); cq[1] = fmaf(v.y, v.y, cq[1]);
            cq[2] = fmaf(v.z, v.z, cq[2]); cq[3] = fmaf(v.w, v.w, cq[3]);
        }
        __syncthreads();   // staging free

        // 8 row-groups x 128 cols partials in staging region
        {
            float4* red = (float4*)(smem + SM_CS);
            red[(tid >> 5) * 32 + (tid & 31)]       = make_float4(cs[0], cs[1], cs[2], cs[3]);
            red[256 + (tid >> 5) * 32 + (tid & 31)] = make_float4(cq[0], cq[1], cq[2], cq[3]);
        }
        __syncthreads();
        if (tid < 128) {
            const float* rs = (const float*)(smem + SM_CS);
            float s = 0.f, q = 0.f;
            #pragma unroll
            for (int g = 0; g < 8; g++) {
                s += rs[g * 128 + tid];
                q += rs[1024 + g * 128 + tid];
            }
            run_s[0] += s;
            run_q[0] += q;
        }
        __syncthreads();
    }

    if (tid < 128) {
        g_stat[b][blockIdx.x][0][tid] = run_s[0];
        g_stat[b][blockIdx.x][1][tid] = run_q[0];
    }
}

// ---------------- 6) finalize stats -> scale/shift ----------------
__global__ void stat_reduce(const float* __restrict__ gamma, const float* __restrict__ beta) {
    const int b = blockIdx.x, g = threadIdx.x;
    float s = 0.f, q = 0.f;
    #pragma unroll
    for (int t = 0; t < GRIDX; t++) {
        s += g_stat[b][t][0][g];
        q += g_stat[b][t][1][g];
    }
    const float inv = 1.f / (float)Ln;
    float m = s * inv;
    float v = q * inv - m * m;
    float rs = rsqrtf(v + 1e-5f);
    float sc = rs * gamma[g];
    g_sc[b][g] = sc;
    g_sh[b][g] = fmaf(-m, sc, beta[g]);
}

// ---------------- 7) final normalize ----------------
__global__ void final_kernel(float* __restrict__ out) {
    int i = blockIdx.x * blockDim.x + threadIdx.x;
    int b = i >> 17;
    int fq = i & 31;
    float4 v = ((const float4*)g_y3)[i];
    float4 s = ((const float4*)&g_sc[b][0])[fq];
    float4 h = ((const float4*)&g_sh[b][0])[fq];
    v.x = fmaf(v.x, s.x, h.x); v.y = fmaf(v.y, s.y, h.y);
    v.z = fmaf(v.z, s.z, h.z); v.w = fmaf(v.w, s.w, h.w);
    ((float4*)out)[i] = v;
}

// ---------------- launch ----------------
extern "C" void kernel_launch(void* const* d_in, const int* in_sizes, int n_in,
                              void* d_out, int out_size) {
    const float* x     = (const float*)d_in[0];
    const float* qw    = (const float*)d_in[1];
    const float* qb    = (const float*)d_in[2];
    const float* kw    = (const float*)d_in[3];
    const float* kb    = (const float*)d_in[4];
    const float* ffw   = (const float*)d_in[5];
    const float* ffb   = (const float*)d_in[6];
    const float* gamma = (const float*)d_in[7];
    const float* beta  = (const float*)d_in[8];
    float* out = (float*)d_out;

    cudaFuncSetAttribute((const void*)mma_gemm<0>,
                         cudaFuncAttributeMaxDynamicSharedMemorySize, GEMM_SMEM);
    cudaFuncSetAttribute((const void*)mma_gemm<1>,
                         cudaFuncAttributeMaxDynamicSharedMemorySize, GEMM_SMEM);

    coef_kernel<<<(Ln + 255) / 256, 256>>>(qw, qb, kw, kb);
    qk_partial<<<dim3(NSPLIT, Bn), 256>>>(x);
    qk_reduce<<<Bn, Fn>>>();
    att_kernel<<<dim3(Fn, Bn), Fn>>>();
    prep_B<<<Bn + 1, 256>>>(ffw);

    mma_gemm<0><<<dim3(GRIDX, Bn), 256, GEMM_SMEM>>>(x, ffb);
    stat_reduce<<<Bn, Fn>>>(gamma, beta);
    mma_gemm<1><<<dim3(GRIDX, Bn), 256, GEMM_SMEM>>>(x, ffb);
    stat_reduce<<<Bn, Fn>>>(gamma, beta);
    final_kernel<<<TOT / 4 / 256, 256>>>(out);
}

// round 4
// speedup vs baseline: 1.0729x; 1.0173x over previous
#include <cuda_runtime.h>
#include <cuda_bf16.h>
#include <cstdint>

#define Bn 32
#define Ln 4096
#define Fn 128
#define NLEV 12
#define NSPLIT 16
#define TILE_L 128
#define LTILES (Ln / TILE_L)            // 32
#define TOT (Bn * Ln * Fn)
#define TILES_PER_CTA 8
#define GRIDX (LTILES / TILES_PER_CTA)  // 4

// smem float offsets: A double-buffered 128x132, B 128x132, red 2048, tables 384
#define FO_A0 0
#define FO_A1 16896
#define FO_B  33792
#define FO_RED 50688
#define FO_TAB 52736
#define GEMM_SMEM ((52736 + 384) * 4)   // 212480 bytes

// ---------------- scratch ----------------
__device__ float g_coef[2][Ln];
__device__ float g_bias[2];
__device__ float g_part[Bn][NSPLIT][2][Fn];
__device__ float g_q[Bn][Fn];
__device__ float g_k[Bn][Fn];
__device__ float g_att[Bn][Fn][Fn];
__device__ float g_x2[TOT];
__device__ float g_y3[TOT];
__device__ float g_stat[Bn][GRIDX][2][Fn];
__device__ float g_sc[Bn][Fn];
__device__ float g_sh[Bn][Fn];
// pre-rounded tf32 B operands, row-major Bt[n][k]: [0..31] att^T, [32] ff_w
__device__ float g_Bt[Bn + 1][Fn * Fn];

__device__ __forceinline__ uint32_t smem_u32(const void* p) {
    uint32_t a;
    asm("{ .reg .u64 t; cvta.to.shared.u64 t, %1; cvt.u32.u64 %0, t; }" : "=r"(a) : "l"(p));
    return a;
}
__device__ __forceinline__ uint32_t f2tf32(float x) {
    uint32_t r;
    asm("cvt.rna.tf32.f32 %0, %1;" : "=r"(r) : "f"(x));
    return r;
}
__device__ __forceinline__ void cp16(uint32_t dst, const void* src) {
    asm volatile("cp.async.cg.shared.global [%0], [%1], 16;" :: "r"(dst), "l"(src));
}
#define CP_COMMIT() asm volatile("cp.async.commit_group;" ::: "memory")
#define CP_WAIT1()  asm volatile("cp.async.wait_group 1;" ::: "memory")

#define MMA_TF32(C, A, b0, b1) \
    asm volatile("mma.sync.aligned.m16n8k8.row.col.f32.tf32.tf32.f32 " \
                 "{%0,%1,%2,%3}, {%4,%5,%6,%7}, {%8,%9}, {%0,%1,%2,%3};" \
                 : "+f"(C[0]), "+f"(C[1]), "+f"(C[2]), "+f"(C[3]) \
                 : "r"(A[0]), "r"(A[1]), "r"(A[2]), "r"(A[3]), "r"(b0), "r"(b1))

// ---------------- 1) wavelet coefficients + biases ----------------
__global__ void coef_kernel(const float* __restrict__ qw, const float* __restrict__ qb,
                            const float* __restrict__ kw, const float* __restrict__ kb) {
    int l = blockIdx.x * blockDim.x + threadIdx.x;
    if (l < Ln) {
        float cq = 1.f, ck = 1.f;
        #pragma unroll
        for (int i = 0; i < NLEV; i++) {
            int bit = (l >> i) & 1;
            cq *= qw[2 * i + bit];
            ck *= kw[2 * i + bit];
        }
        g_coef[0][l] = cq;
        g_coef[1][l] = ck;
    }
    if (blockIdx.x == 0 && threadIdx.x == 0) {
        float bq = qb[NLEV - 1], bk = kb[NLEV - 1], pq = 1.f, pk = 1.f;
        for (int i = NLEV - 2; i >= 0; i--) {
            pq *= (qw[2 * (i + 1)] + qw[2 * (i + 1) + 1]);
            pk *= (kw[2 * (i + 1)] + kw[2 * (i + 1) + 1]);
            bq += qb[i] * pq;
            bk += kb[i] * pk;
        }
        g_bias[0] = bq;
        g_bias[1] = bk;
    }
}

// ---------------- 2) q/k reductions ----------------
__global__ void qk_partial(const float* __restrict__ x) {
    const int b = blockIdx.y, ls = blockIdx.x;
    const int tid = threadIdx.x;
    const int f = tid & 127, sub = tid >> 7;
    const int lbase = ls * 256 + sub * 128;
    const float* xp = x + ((size_t)b * Ln + lbase) * Fn + f;
    float aq = 0.f, ak = 0.f;
    #pragma unroll 4
    for (int j = 0; j < 128; j++) {
        float xv = xp[(size_t)j * Fn];
        int l = lbase + j;
        aq = fmaf(g_coef[0][l], xv, aq);
        ak = fmaf(g_coef[1][l], xv, ak);
    }
    __shared__ float sq[256], sk[256];
    sq[tid] = aq; sk[tid] = ak;
    __syncthreads();
    if (tid < 128) {
        g_part[b][ls][0][tid] = sq[tid] + sq[tid + 128];
        g_part[b][ls][1][tid] = sk[tid] + sk[tid + 128];
    }
}

__global__ void qk_reduce() {
    const int b = blockIdx.x, f = threadIdx.x;
    float q = g_bias[0], k = g_bias[1];
    #pragma unroll
    for (int s = 0; s < NSPLIT; s++) {
        q += g_part[b][s][0][f];
        k += g_part[b][s][1][f];
    }
    g_q[b][f] = q;
    g_k[b][f] = k;
}

// ---------------- 3) attention softmax ----------------
__global__ void att_kernel() {
    const int b = blockIdx.y, f = blockIdx.x, g = threadIdx.x;
    const float scale = 0.08838834764831845f;
    float s = g_q[b][f] * g_k[b][g] * scale;
    __shared__ float sm[Fn];
    sm[g] = s;
    __syncthreads();
    for (int o = 64; o > 0; o >>= 1) {
        if (g < o) sm[g] = fmaxf(sm[g], sm[g + o]);
        __syncthreads();
    }
    float mx = sm[0];
    __syncthreads();
    float e = expf(s - mx);
    sm[g] = e;
    __syncthreads();
    for (int o = 64; o > 0; o >>= 1) {
        if (g < o) sm[g] += sm[g + o];
        __syncthreads();
    }
    g_att[b][f][g] = e / sm[0];
}

// ---------------- 4) B operands: Bt[n][k], pre-rounded to tf32 ----------------
__global__ void prep_B(const float* __restrict__ ffw) {
    int b = blockIdx.x;
    for (int idx = threadIdx.x; idx < Fn * Fn; idx += blockDim.x) {
        int n = idx >> 7, k = idx & 127;
        float v = (b < Bn) ? g_att[b][k][n] : ffw[n * Fn + k];
        g_Bt[b][idx] = __uint_as_float(f2tf32(v));
    }
}

// ---------------- 5) tf32 mma GEMM, cp.async pipelined, fused stats ----------------
// MODE 0: x2 = x + x @ att          MODE 1: y3 = y2 + y2 @ ff_w^T + ffb, y2 = x2*sc+sh
template <int MODE>
__global__ __launch_bounds__(256, 1)
void mma_gemm(const float* __restrict__ xin, const float* __restrict__ ffb) {
    extern __shared__ float sm[];
    float* const Abuf[2] = { sm + FO_A0, sm + FO_A1 };
    float* const Bb  = sm + FO_B;
    float* const red = sm + FO_RED;
    float* const tab = sm + FO_TAB;

    const int tid = threadIdx.x, lane = tid & 31, w = tid >> 5;
    const int gid = lane >> 2, tig = lane & 3;
    const int wm = w & 3, wn = w >> 2;
    const int b = blockIdx.y;

    const float* Xin = (MODE == 0 ? xin : g_x2) + ((size_t)b * Ln + (size_t)blockIdx.x * TILES_PER_CTA * TILE_L) * Fn;
    float* Xout = (MODE == 0 ? g_x2 : g_y3) + ((size_t)b * Ln + (size_t)blockIdx.x * TILES_PER_CTA * TILE_L) * Fn;

    const uint32_t abuf_u32[2] = { smem_u32(Abuf[0]), smem_u32(Abuf[1]) };

    // prologue: cp.async tile 0
    #pragma unroll
    for (int i = tid; i < 4096; i += 256)
        cp16(abuf_u32[0] + ((i >> 5) * 132 + (i & 31) * 4) * 4, Xin + (size_t)i * 4);
    CP_COMMIT();

    // load B tile (restride 128 -> 132)
    {
        const float4* Bg = (const float4*)&g_Bt[MODE == 0 ? b : Bn][0];
        #pragma unroll
        for (int i = tid; i < 4096; i += 256)
            *(float4*)&Bb[(i >> 5) * 132 + (i & 31) * 4] = Bg[i];
    }
    // tables
    if (MODE == 1 && tid < 128) {
        tab[tid] = g_sc[b][tid];
        tab[128 + tid] = g_sh[b][tid];
        tab[256 + tid] = g_sh[b][tid] + ffb[tid];
    }
    __syncthreads();

    // per-thread residual affine params (cols fixed per ni)
    float rscx[8], rscy[8], rshx[8], rshy[8];
    if (MODE == 1) {
        #pragma unroll
        for (int ni = 0; ni < 8; ni++) {
            int cb = wn * 64 + ni * 8 + tig * 2;
            rscx[ni] = tab[cb];       rscy[ni] = tab[cb + 1];
            rshx[ni] = tab[256 + cb]; rshy[ni] = tab[256 + cb + 1];
        }
    }

    float run_s = 0.f, run_q = 0.f;   // per (tid<128) feature accumulators
    float4 cs4, cq4;

    for (int t = 0; t < TILES_PER_CTA; t++) {
        // prefetch next tile
        if (t + 1 < TILES_PER_CTA) {
            const float* src = Xin + (size_t)(t + 1) * TILE_L * Fn;
            #pragma unroll
            for (int i = tid; i < 4096; i += 256)
                cp16(abuf_u32[(t + 1) & 1] + ((i >> 5) * 132 + (i & 31) * 4) * 4, src + (size_t)i * 4);
        }
        CP_COMMIT();
        CP_WAIT1();
        __syncthreads();

        float* const buf = Abuf[t & 1];

        // ---- mma mainloop: 16 k-steps ----
        float c[2][8][4];
        #pragma unroll
        for (int mi = 0; mi < 2; mi++)
            #pragma unroll
            for (int ni = 0; ni < 8; ni++)
                #pragma unroll
                for (int j = 0; j < 4; j++) c[mi][ni][j] = 0.f;

        #pragma unroll
        for (int ks = 0; ks < 16; ks++) {
            const int k0 = ks * 8;
            float sca0 = 1.f, sca4 = 1.f, sha0 = 0.f, sha4 = 0.f;
            if (MODE == 1) {
                sca0 = tab[k0 + tig];       sca4 = tab[k0 + tig + 4];
                sha0 = tab[128 + k0 + tig]; sha4 = tab[128 + k0 + tig + 4];
            }
            uint32_t a[2][4];
            #pragma unroll
            for (int mi = 0; mi < 2; mi++) {
                const float* Ar = buf + (wm * 32 + mi * 16 + gid) * 132 + k0 + tig;
                float x0 = Ar[0], x1 = Ar[8 * 132], x2 = Ar[4], x3 = Ar[8 * 132 + 4];
                if (MODE == 1) {
                    x0 = fmaf(x0, sca0, sha0); x1 = fmaf(x1, sca0, sha0);
                    x2 = fmaf(x2, sca4, sha4); x3 = fmaf(x3, sca4, sha4);
                }
                a[mi][0] = f2tf32(x0); a[mi][1] = f2tf32(x1);
                a[mi][2] = f2tf32(x2); a[mi][3] = f2tf32(x3);
            }
            #pragma unroll
            for (int ni = 0; ni < 8; ni++) {
                const float* Br = Bb + (wn * 64 + ni * 8 + gid) * 132 + k0 + tig;
                uint32_t b0 = __float_as_uint(Br[0]);
                uint32_t b1 = __float_as_uint(Br[4]);
                MMA_TF32(c[0][ni], a[0], b0, b1);
                MMA_TF32(c[1][ni], a[1], b0, b1);
            }
        }
        __syncthreads();   // all A-frag reads done before RMW overwrites

        // ---- RMW epilogue: out = mma + residual(+bias), in place in A buffer ----
        #pragma unroll
        for (int mi = 0; mi < 2; mi++)
            #pragma unroll
            for (int ni = 0; ni < 8; ni++) {
                float* p = buf + (wm * 32 + mi * 16 + gid) * 132 + wn * 64 + ni * 8 + tig * 2;
                float2 v0 = *(float2*)p;
                float2 v1 = *(float2*)(p + 8 * 132);
                float r0x, r0y, r1x, r1y;
                if (MODE == 1) {
                    r0x = fmaf(v0.x, rscx[ni], rshx[ni]); r0y = fmaf(v0.y, rscy[ni], rshy[ni]);
                    r1x = fmaf(v1.x, rscx[ni], rshx[ni]); r1y = fmaf(v1.y, rscy[ni], rshy[ni]);
                } else {
                    r0x = v0.x; r0y = v0.y; r1x = v1.x; r1y = v1.y;
                }
                *(float2*)p = make_float2(c[mi][ni][0] + r0x, c[mi][ni][1] + r0y);
                *(float2*)(p + 8 * 132) = make_float2(c[mi][ni][2] + r1x, c[mi][ni][3] + r1y);
            }
        __syncthreads();

        // ---- coalesced store + column stats ----
        cs4 = make_float4(0.f, 0.f, 0.f, 0.f);
        cq4 = make_float4(0.f, 0.f, 0.f, 0.f);
        float4* Y4 = (float4*)(Xout + (size_t)t * TILE_L * Fn);
        #pragma unroll
        for (int j = 0; j < 16; j++) {
            int i = tid + 256 * j;
            float4 v = *(float4*)&buf[(i >> 5) * 132 + (i & 31) * 4];
            Y4[i] = v;
            cs4.x += v.x; cs4.y += v.y; cs4.z += v.z; cs4.w += v.w;
            cq4.x = fmaf(v.x, v.x, cq4.x); cq4.y = fmaf(v.y, v.y, cq4.y);
            cq4.z = fmaf(v.z, v.z, cq4.z); cq4.w = fmaf(v.w, v.w, cq4.w);
        }
        ((float4*)red)[(tid >> 5) * 32 + (tid & 31)]       = cs4;
        ((float4*)red)[256 + (tid >> 5) * 32 + (tid & 31)] = cq4;
        __syncthreads();
        if (tid < 128) {
            float s = 0.f, q = 0.f;
            #pragma unroll
            for (int g = 0; g < 8; g++) {
                s += red[g * 128 + tid];
                q += red[1024 + g * 128 + tid];
            }
            run_s += s;
            run_q += q;
        }
        __syncthreads();
    }

    if (tid < 128) {
        g_stat[b][blockIdx.x][0][tid] = run_s;
        g_stat[b][blockIdx.x][1][tid] = run_q;
    }
}

// ---------------- 6) finalize stats -> scale/shift ----------------
__global__ void stat_reduce(const float* __restrict__ gamma, const float* __restrict__ beta) {
    const int b = blockIdx.x, g = threadIdx.x;
    float s = 0.f, q = 0.f;
    #pragma unroll
    for (int t = 0; t < GRIDX; t++) {
        s += g_stat[b][t][0][g];
        q += g_stat[b][t][1][g];
    }
    const float inv = 1.f / (float)Ln;
    float m = s * inv;
    float v = q * inv - m * m;
    float rs = rsqrtf(v + 1e-5f);
    float sc = rs * gamma[g];
    g_sc[b][g] = sc;
    g_sh[b][g] = fmaf(-m, sc, beta[g]);
}

// ---------------- 7) final normalize ----------------
__global__ void final_kernel(float* __restrict__ out) {
    int i = blockIdx.x * blockDim.x + threadIdx.x;
    int b = i >> 17;
    int fq = i & 31;
    float4 v = ((const float4*)g_y3)[i];
    float4 s = ((const float4*)&g_sc[b][0])[fq];
    float4 h = ((const float4*)&g_sh[b][0])[fq];
    v.x = fmaf(v.x, s.x, h.x); v.y = fmaf(v.y, s.y, h.y);
    v.z = fmaf(v.z, s.z, h.z); v.w = fmaf(v.w, s.w, h.w);
    ((float4*)out)[i] = v;
}

// ---------------- launch ----------------
extern "C" void kernel_launch(void* const* d_in, const int* in_sizes, int n_in,
                              void* d_out, int out_size) {
    const float* x     = (const float*)d_in[0];
    const float* qw    = (const float*)d_in[1];
    const float* qb    = (const float*)d_in[2];
    const float* kw    = (const float*)d_in[3];
    const float* kb    = (const float*)d_in[4];
    const float* ffw   = (const float*)d_in[5];
    const float* ffb   = (const float*)d_in[6];
    const float* gamma = (const float*)d_in[7];
    const float* beta  = (const float*)d_in[8];
    float* out = (float*)d_out;

    cudaFuncSetAttribute((const void*)mma_gemm<0>,
                         cudaFuncAttributeMaxDynamicSharedMemorySize, GEMM_SMEM);
    cudaFuncSetAttribute((const void*)mma_gemm<1>,
                         cudaFuncAttributeMaxDynamicSharedMemorySize, GEMM_SMEM);

    coef_kernel<<<(Ln + 255) / 256, 256>>>(qw, qb, kw, kb);
    qk_partial<<<dim3(NSPLIT, Bn), 256>>>(x);
    qk_reduce<<<Bn, Fn>>>();
    att_kernel<<<dim3(Fn, Bn), Fn>>>();
    prep_B<<<Bn + 1, 256>>>(ffw);

    mma_gemm<0><<<dim3(GRIDX, Bn), 256, GEMM_SMEM>>>(x, ffb);
    stat_reduce<<<Bn, Fn>>>(gamma, beta);
    mma_gemm<1><<<dim3(GRIDX, Bn), 256, GEMM_SMEM>>>(x, ffb);
    stat_reduce<<<Bn, Fn>>>(gamma, beta);
    final_kernel<<<TOT / 4 / 256, 256>>>(out);
}

// round 5
// speedup vs baseline: 1.4882x; 1.3870x over previous
#include <cuda_runtime.h>
#include <cstdint>

#define Bn 32
#define Ln 4096
#define Fn 128
#define NLEV 12
#define NSPLIT 16
#define TILE_L 128
#define LTILES (Ln / TILE_L)            // 32
#define TOT (Bn * Ln * Fn)
#define TILES_PER_CTA 8
#define GRIDX (LTILES / TILES_PER_CTA)  // 4

// smem float offsets (GEMM): A double-buffered 128x132, B 128x132, red 4096
#define FO_A1 16896
#define FO_B  33792
#define FO_RED 50688
#define GEMM_SMEM ((50688 + 4096) * 4)  // 219136 bytes

#define ATT_SMEM (128 * 132 * 4 + 1024) // att tile + k/rinv

// ---------------- scratch ----------------
__device__ float g_coef[2][Ln];
__device__ float g_bias[2];
__device__ float g_part[Bn][NSPLIT][2][Fn];
__device__ float g_x2[TOT];
__device__ float g_y3[TOT];
__device__ float g_stat[Bn][GRIDX][2][Fn];
__device__ float g_sc[Bn][Fn];
__device__ float g_sh[Bn][Fn];
__device__ float g_rsh[Bn][Fn];          // sh + ffb + sh@W^T   (epilogue shift, GEMM1)
__device__ float g_Bt[Bn][Fn * Fn];      // att^T, tf32-rounded (GEMM0 B)
__device__ float g_Bt2[Bn][Fn * Fn];     // (sc*W), tf32-rounded (GEMM1 B)

__device__ __forceinline__ uint32_t smem_u32(const void* p) {
    uint32_t a;
    asm("{ .reg .u64 t; cvta.to.shared.u64 t, %1; cvt.u32.u64 %0, t; }" : "=r"(a) : "l"(p));
    return a;
}
__device__ __forceinline__ uint32_t f2tf32(float x) {
    uint32_t r;
    asm("cvt.rna.tf32.f32 %0, %1;" : "=r"(r) : "f"(x));
    return r;
}
__device__ __forceinline__ void cp16(uint32_t dst, const void* src) {
    asm volatile("cp.async.cg.shared.global [%0], [%1], 16;" :: "r"(dst), "l"(src));
}
#define CP_COMMIT() asm volatile("cp.async.commit_group;" ::: "memory")
#define CP_WAIT1()  asm volatile("cp.async.wait_group 1;" ::: "memory")

#define MMA_TF32(C, A, b0, b1) \
    asm volatile("mma.sync.aligned.m16n8k8.row.col.f32.tf32.tf32.f32 " \
                 "{%0,%1,%2,%3}, {%4,%5,%6,%7}, {%8,%9}, {%0,%1,%2,%3};" \
                 : "+f"(C[0]), "+f"(C[1]), "+f"(C[2]), "+f"(C[3]) \
                 : "r"(A[0]), "r"(A[1]), "r"(A[2]), "r"(A[3]), "r"(b0), "r"(b1))

// ---------------- 1) wavelet coefficients + biases ----------------
__global__ void coef_kernel(const float* __restrict__ qw, const float* __restrict__ qb,
                            const float* __restrict__ kw, const float* __restrict__ kb) {
    int l = blockIdx.x * blockDim.x + threadIdx.x;
    if (l < Ln) {
        float cq = 1.f, ck = 1.f;
        #pragma unroll
        for (int i = 0; i < NLEV; i++) {
            int bit = (l >> i) & 1;
            cq *= qw[2 * i + bit];
            ck *= kw[2 * i + bit];
        }
        g_coef[0][l] = cq;
        g_coef[1][l] = ck;
    }
    if (blockIdx.x == 0 && threadIdx.x == 0) {
        float bq = qb[NLEV - 1], bk = kb[NLEV - 1], pq = 1.f, pk = 1.f;
        for (int i = NLEV - 2; i >= 0; i--) {
            pq *= (qw[2 * (i + 1)] + qw[2 * (i + 1) + 1]);
            pk *= (kw[2 * (i + 1)] + kw[2 * (i + 1) + 1]);
            bq += qb[i] * pq;
            bk += kb[i] * pk;
        }
        g_bias[0] = bq;
        g_bias[1] = bk;
    }
}

// ---------------- 2) q/k partial reductions over L ----------------
__global__ void qk_partial(const float* __restrict__ x) {
    const int b = blockIdx.y, ls = blockIdx.x;
    const int tid = threadIdx.x;
    const int f = tid & 127, sub = tid >> 7;
    const int lbase = ls * 256 + sub * 128;
    const float* xp = x + ((size_t)b * Ln + lbase) * Fn + f;
    float aq = 0.f, ak = 0.f;
    #pragma unroll 4
    for (int j = 0; j < 128; j++) {
        float xv = xp[(size_t)j * Fn];
        int l = lbase + j;
        aq = fmaf(g_coef[0][l], xv, aq);
        ak = fmaf(g_coef[1][l], xv, ak);
    }
    __shared__ float sq[256], sk[256];
    sq[tid] = aq; sk[tid] = ak;
    __syncthreads();
    if (tid < 128) {
        g_part[b][ls][0][tid] = sq[tid] + sq[tid + 128];
        g_part[b][ls][1][tid] = sk[tid] + sk[tid + 128];
    }
}

// ---------------- 3) fused: q/k finalize + softmax + B0 prep ----------------
__global__ void att_prep() {
    extern __shared__ float sm[];
    float* at   = sm;                 // 128 x 132 exp values
    float* kk   = sm + 128 * 132;     // k vector
    float* rinv = kk + 128;           // per-row 1/sum
    const int b = blockIdx.x, f = threadIdx.x;

    float q = g_bias[0], k = g_bias[1];
    #pragma unroll
    for (int s = 0; s < NSPLIT; s++) {
        q += g_part[b][s][0][f];
        k += g_part[b][s][1][f];
    }
    kk[f] = k;
    __syncthreads();

    const float t = q * 0.08838834764831845f;   // s * q_f
    float m = -1e30f;
    #pragma unroll 4
    for (int g = 0; g < 128; g++) m = fmaxf(m, t * kk[g]);
    float sum = 0.f;
    #pragma unroll 4
    for (int g = 0; g < 128; g++) {
        float e = expf(t * kk[g] - m);
        at[f * 132 + g] = e;
        sum += e;
    }
    rinv[f] = 1.f / sum;
    __syncthreads();

    // g_Bt[b][n*128+k] = att[k][n] / sum_k   (tf32-rounded)
    for (int idx = f; idx < Fn * Fn; idx += 128) {
        int n = idx >> 7, kx = idx & 127;
        g_Bt[b][idx] = __uint_as_float(f2tf32(at[kx * 132 + n] * rinv[kx]));
    }
}

// ---------------- 4) GEMM1 operand prep: B' = sc*W, rsh = sh+ffb+sh@W^T ----------------
__global__ void prep2(const float* __restrict__ ffw, const float* __restrict__ ffb) {
    __shared__ float ssh[Fn], ssc[Fn];
    const int b = blockIdx.x, g = threadIdx.x;
    ssh[g] = g_sh[b][g];
    ssc[g] = g_sc[b][g];
    __syncthreads();
    float bias2 = ffb[g];
    #pragma unroll 4
    for (int k = 0; k < Fn; k++) bias2 = fmaf(ssh[k], ffw[g * Fn + k], bias2);
    g_rsh[b][g] = ssh[g] + bias2;
    for (int idx = g; idx < Fn * Fn; idx += 128)
        g_Bt2[b][idx] = __uint_as_float(f2tf32(ffw[idx] * ssc[idx & 127]));
}

// ---------------- 5) unified tf32 GEMM + residual-affine + fused stats ----------------
// out = (A @ B^T) + A*rsc + rsh ; MODE0: rsc=1, rsh=0
template <int MODE>
__global__ __launch_bounds__(512, 1)
void mma_gemm(const float* __restrict__ xin) {
    extern __shared__ float sm[];
    float* const Abuf[2] = { sm, sm + FO_A1 };
    float* const Bb  = sm + FO_B;
    float* const red = sm + FO_RED;

    const int tid = threadIdx.x, lane = tid & 31, w = tid >> 5;
    const int gid = lane >> 2, tig = lane & 3;
    const int wm = w & 3, wn = w >> 2;
    const int b = blockIdx.y;

    const size_t base = ((size_t)b * Ln + (size_t)blockIdx.x * TILES_PER_CTA * TILE_L) * Fn;
    const float* Xin = (MODE == 0 ? xin : g_x2) + base;
    float* Xout = (MODE == 0 ? g_x2 : g_y3) + base;

    const uint32_t ab32[2] = { smem_u32(Abuf[0]), smem_u32(Abuf[1]) };

    // prologue cp.async tile 0 (8 ops/thread)
    #pragma unroll
    for (int i = tid; i < 4096; i += 512)
        cp16(ab32[0] + ((i >> 5) * 132 + (i & 31) * 4) * 4, Xin + (size_t)i * 4);
    CP_COMMIT();

    // B tile (restride 128 -> 132)
    {
        const float4* Bg = (const float4*)(MODE == 0 ? &g_Bt[b][0] : &g_Bt2[b][0]);
        #pragma unroll
        for (int i = tid; i < 4096; i += 512)
            *(float4*)&Bb[(i >> 5) * 132 + (i & 31) * 4] = Bg[i];
    }

    // epilogue affine params (per thread, fixed columns)
    float rscx[4], rscy[4], rshx[4], rshy[4];
    #pragma unroll
    for (int ni = 0; ni < 4; ni++) {
        if (MODE == 1) {
            int cb = wn * 32 + ni * 8 + tig * 2;
            rscx[ni] = g_sc[b][cb];  rscy[ni] = g_sc[b][cb + 1];
            rshx[ni] = g_rsh[b][cb]; rshy[ni] = g_rsh[b][cb + 1];
        } else {
            rscx[ni] = 1.f; rscy[ni] = 1.f; rshx[ni] = 0.f; rshy[ni] = 0.f;
        }
    }

    float run_s = 0.f, run_q = 0.f;

    for (int t = 0; t < TILES_PER_CTA; t++) {
        if (t + 1 < TILES_PER_CTA) {
            const float* src = Xin + (size_t)(t + 1) * TILE_L * Fn;
            #pragma unroll
            for (int i = tid; i < 4096; i += 512)
                cp16(ab32[(t + 1) & 1] + ((i >> 5) * 132 + (i & 31) * 4) * 4, src + (size_t)i * 4);
        }
        CP_COMMIT();
        CP_WAIT1();
        __syncthreads();

        float* const buf = Abuf[t & 1];

        float c[2][4][4];
        #pragma unroll
        for (int mi = 0; mi < 2; mi++)
            #pragma unroll
            for (int ni = 0; ni < 4; ni++)
                #pragma unroll
                for (int j = 0; j < 4; j++) c[mi][ni][j] = 0.f;

        #pragma unroll
        for (int ks = 0; ks < 16; ks++) {
            const int k0 = ks * 8;
            uint32_t a[2][4];
            #pragma unroll
            for (int mi = 0; mi < 2; mi++) {
                const float* Ar = buf + (wm * 32 + mi * 16 + gid) * 132 + k0 + tig;
                a[mi][0] = f2tf32(Ar[0]);
                a[mi][1] = f2tf32(Ar[8 * 132]);
                a[mi][2] = f2tf32(Ar[4]);
                a[mi][3] = f2tf32(Ar[8 * 132 + 4]);
            }
            #pragma unroll
            for (int ni = 0; ni < 4; ni++) {
                const float* Br = Bb + (wn * 32 + ni * 8 + gid) * 132 + k0 + tig;
                uint32_t b0 = __float_as_uint(Br[0]);
                uint32_t b1 = __float_as_uint(Br[4]);
                MMA_TF32(c[0][ni], a[0], b0, b1);
                MMA_TF32(c[1][ni], a[1], b0, b1);
            }
        }
        __syncthreads();

        // RMW epilogue in place: out = mma + x*rsc + rsh
        #pragma unroll
        for (int mi = 0; mi < 2; mi++)
            #pragma unroll
            for (int ni = 0; ni < 4; ni++) {
                float* p = buf + (wm * 32 + mi * 16 + gid) * 132 + wn * 32 + ni * 8 + tig * 2;
                float2 v0 = *(float2*)p;
                float2 v1 = *(float2*)(p + 8 * 132);
                *(float2*)p = make_float2(fmaf(v0.x, rscx[ni], rshx[ni]) + c[mi][ni][0],
                                          fmaf(v0.y, rscy[ni], rshy[ni]) + c[mi][ni][1]);
                *(float2*)(p + 8 * 132) = make_float2(fmaf(v1.x, rscx[ni], rshx[ni]) + c[mi][ni][2],
                                                      fmaf(v1.y, rscy[ni], rshy[ni]) + c[mi][ni][3]);
            }
        __syncthreads();

        // coalesced store + column stats
        float4 cs4 = make_float4(0.f, 0.f, 0.f, 0.f);
        float4 cq4 = make_float4(0.f, 0.f, 0.f, 0.f);
        float4* Y4 = (float4*)(Xout + (size_t)t * TILE_L * Fn);
        #pragma unroll
        for (int j = 0; j < 8; j++) {
            int i = tid + 512 * j;
            float4 v = *(float4*)&buf[(i >> 5) * 132 + (i & 31) * 4];
            Y4[i] = v;
            cs4.x += v.x; cs4.y += v.y; cs4.z += v.z; cs4.w += v.w;
            cq4.x = fmaf(v.x, v.x, cq4.x); cq4.y = fmaf(v.y, v.y, cq4.y);
            cq4.z = fmaf(v.z, v.z, cq4.z); cq4.w = fmaf(v.w, v.w, cq4.w);
        }
        ((float4*)red)[tid]       = cs4;
        ((float4*)red)[512 + tid] = cq4;
        __syncthreads();
        if (tid < 128) {
            float s = 0.f, q = 0.f;
            #pragma unroll
            for (int g = 0; g < 16; g++) {
                s += red[g * 128 + tid];
                q += red[2048 + g * 128 + tid];
            }
            run_s += s;
            run_q += q;
        }
    }

    if (tid < 128) {
        g_stat[b][blockIdx.x][0][tid] = run_s;
        g_stat[b][blockIdx.x][1][tid] = run_q;
    }
}

// ---------------- 6) finalize stats -> scale/shift ----------------
__global__ void stat_reduce(const float* __restrict__ gamma, const float* __restrict__ beta) {
    const int b = blockIdx.x, g = threadIdx.x;
    float s = 0.f, q = 0.f;
    #pragma unroll
    for (int t = 0; t < GRIDX; t++) {
        s += g_stat[b][t][0][g];
        q += g_stat[b][t][1][g];
    }
    const float inv = 1.f / (float)Ln;
    float m = s * inv;
    float v = q * inv - m * m;
    float rs = rsqrtf(v + 1e-5f);
    float sc = rs * gamma[g];
    g_sc[b][g] = sc;
    g_sh[b][g] = fmaf(-m, sc, beta[g]);
}

// ---------------- 7) final normalize ----------------
__global__ void final_kernel(float* __restrict__ out) {
    int i = blockIdx.x * blockDim.x + threadIdx.x;
    int b = i >> 17;
    int fq = i & 31;
    float4 v = ((const float4*)g_y3)[i];
    float4 s = ((const float4*)&g_sc[b][0])[fq];
    float4 h = ((const float4*)&g_sh[b][0])[fq];
    v.x = fmaf(v.x, s.x, h.x); v.y = fmaf(v.y, s.y, h.y);
    v.z = fmaf(v.z, s.z, h.z); v.w = fmaf(v.w, s.w, h.w);
    ((float4*)out)[i] = v;
}

// ---------------- launch ----------------
extern "C" void kernel_launch(void* const* d_in, const int* in_sizes, int n_in,
                              void* d_out, int out_size) {
    const float* x     = (const float*)d_in[0];
    const float* qw    = (const float*)d_in[1];
    const float* qb    = (const float*)d_in[2];
    const float* kw    = (const float*)d_in[3];
    const float* kb    = (const float*)d_in[4];
    const float* ffw   = (const float*)d_in[5];
    const float* ffb   = (const float*)d_in[6];
    const float* gamma = (const float*)d_in[7];
    const float* beta  = (const float*)d_in[8];
    float* out = (float*)d_out;

    cudaFuncSetAttribute((const void*)mma_gemm<0>,
                         cudaFuncAttributeMaxDynamicSharedMemorySize, GEMM_SMEM);
    cudaFuncSetAttribute((const void*)mma_gemm<1>,
                         cudaFuncAttributeMaxDynamicSharedMemorySize, GEMM_SMEM);
    cudaFuncSetAttribute((const void*)att_prep,
                         cudaFuncAttributeMaxDynamicSharedMemorySize, ATT_SMEM);

    coef_kernel<<<(Ln + 255) / 256, 256>>>(qw, qb, kw, kb);
    qk_partial<<<dim3(NSPLIT, Bn), 256>>>(x);
    att_prep<<<Bn, 128, ATT_SMEM>>>();
    mma_gemm<0><<<dim3(GRIDX, Bn), 512, GEMM_SMEM>>>(x);
    stat_reduce<<<Bn, Fn>>>(gamma, beta);
    prep2<<<Bn, Fn>>>(ffw, ffb);
    mma_gemm<1><<<dim3(GRIDX, Bn), 512, GEMM_SMEM>>>(x);
    stat_reduce<<<Bn, Fn>>>(gamma, beta);
    final_kernel<<<TOT / 4 / 256, 256>>>(out);
}

// round 6
// speedup vs baseline: 1.5697x; 1.0547x over previous
#include <cuda_runtime.h>
#include <cstdint>

#define Bn 32
#define Ln 4096
#define Fn 128
#define NLEV 12
#define NSPLIT 16
#define TILE_L 128
#define LTILES (Ln / TILE_L)            // 32
#define TOT (Bn * Ln * Fn)
#define TILES_PER_CTA 8
#define GRIDX (LTILES / TILES_PER_CTA)  // 4

// smem float offsets: A double-buffered 128x132, packed B 16384, red 1024
#define FO_A1 16896
#define FO_B  33792
#define FO_RED 50176
#define GEMM_SMEM ((50176 + 1024) * 4)  // 204800 bytes

#define ATT_SMEM (128 * 132 * 4 + 1024)

// ---------------- scratch ----------------
__device__ float g_coef[2][Ln];
__device__ float g_bias[2];
__device__ float g_part[Bn][NSPLIT][2][Fn];
__device__ float g_x2[TOT];
__device__ float g_y3[TOT];
__device__ float g_stat[Bn][GRIDX][2][Fn];
__device__ float g_sc[Bn][Fn];
__device__ float g_sh[Bn][Fn];
__device__ float g_rsh[Bn][Fn];          // sh + ffb + sh@W^T
__device__ float g_Bt[Bn][Fn * Fn];      // att^T, tf32-rounded (GEMM0 B)
__device__ float g_Bt2[Bn][Fn * Fn];     // sc*W,  tf32-rounded (GEMM1 B)

__device__ __forceinline__ uint32_t smem_u32(const void* p) {
    uint32_t a;
    asm("{ .reg .u64 t; cvta.to.shared.u64 t, %1; cvt.u32.u64 %0, t; }" : "=r"(a) : "l"(p));
    return a;
}
__device__ __forceinline__ uint32_t f2tf32(float x) {
    uint32_t r;
    asm("cvt.rna.tf32.f32 %0, %1;" : "=r"(r) : "f"(x));
    return r;
}
__device__ __forceinline__ void cp16(uint32_t dst, const void* src) {
    asm volatile("cp.async.cg.shared.global [%0], [%1], 16;" :: "r"(dst), "l"(src));
}
#define CP_COMMIT() asm volatile("cp.async.commit_group;" ::: "memory")
#define CP_WAIT1()  asm volatile("cp.async.wait_group 1;" ::: "memory")

#define MMA_TF32(C, A, b0, b1) \
    asm volatile("mma.sync.aligned.m16n8k8.row.col.f32.tf32.tf32.f32 " \
                 "{%0,%1,%2,%3}, {%4,%5,%6,%7}, {%8,%9}, {%0,%1,%2,%3};" \
                 : "+f"(C[0]), "+f"(C[1]), "+f"(C[2]), "+f"(C[3]) \
                 : "r"(A[0]), "r"(A[1]), "r"(A[2]), "r"(A[3]), "r"(b0), "r"(b1))

// ---------------- 1) wavelet coefficients + biases ----------------
__global__ void coef_kernel(const float* __restrict__ qw, const float* __restrict__ qb,
                            const float* __restrict__ kw, const float* __restrict__ kb) {
    int l = blockIdx.x * blockDim.x + threadIdx.x;
    if (l < Ln) {
        float cq = 1.f, ck = 1.f;
        #pragma unroll
        for (int i = 0; i < NLEV; i++) {
            int bit = (l >> i) & 1;
            cq *= qw[2 * i + bit];
            ck *= kw[2 * i + bit];
        }
        g_coef[0][l] = cq;
        g_coef[1][l] = ck;
    }
    if (blockIdx.x == 0 && threadIdx.x == 0) {
        float bq = qb[NLEV - 1], bk = kb[NLEV - 1], pq = 1.f, pk = 1.f;
        for (int i = NLEV - 2; i >= 0; i--) {
            pq *= (qw[2 * (i + 1)] + qw[2 * (i + 1) + 1]);
            pk *= (kw[2 * (i + 1)] + kw[2 * (i + 1) + 1]);
            bq += qb[i] * pq;
            bk += kb[i] * pk;
        }
        g_bias[0] = bq;
        g_bias[1] = bk;
    }
}

// ---------------- 2) q/k partial reductions over L ----------------
__global__ void qk_partial(const float* __restrict__ x) {
    const int b = blockIdx.y, ls = blockIdx.x;
    const int tid = threadIdx.x;
    const int f = tid & 127, sub = tid >> 7;
    const int lbase = ls * 256 + sub * 128;
    const float* xp = x + ((size_t)b * Ln + lbase) * Fn + f;
    float aq = 0.f, ak = 0.f;
    #pragma unroll 4
    for (int j = 0; j < 128; j++) {
        float xv = xp[(size_t)j * Fn];
        int l = lbase + j;
        aq = fmaf(g_coef[0][l], xv, aq);
        ak = fmaf(g_coef[1][l], xv, ak);
    }
    __shared__ float sq[256], sk[256];
    sq[tid] = aq; sk[tid] = ak;
    __syncthreads();
    if (tid < 128) {
        g_part[b][ls][0][tid] = sq[tid] + sq[tid + 128];
        g_part[b][ls][1][tid] = sk[tid] + sk[tid + 128];
    }
}

// ---------------- 3) fused: q/k finalize + softmax + B0 prep ----------------
__global__ void att_prep() {
    extern __shared__ float sm[];
    float* at   = sm;
    float* kk   = sm + 128 * 132;
    float* rinv = kk + 128;
    const int b = blockIdx.x, f = threadIdx.x;

    float q = g_bias[0], k = g_bias[1];
    #pragma unroll
    for (int s = 0; s < NSPLIT; s++) {
        q += g_part[b][s][0][f];
        k += g_part[b][s][1][f];
    }
    kk[f] = k;
    __syncthreads();

    const float t = q * 0.08838834764831845f;
    float m = -1e30f;
    #pragma unroll 4
    for (int g = 0; g < 128; g++) m = fmaxf(m, t * kk[g]);
    float sum = 0.f;
    #pragma unroll 4
    for (int g = 0; g < 128; g++) {
        float e = expf(t * kk[g] - m);
        at[f * 132 + g] = e;
        sum += e;
    }
    rinv[f] = 1.f / sum;
    __syncthreads();

    for (int idx = f; idx < Fn * Fn; idx += 128) {
        int n = idx >> 7, kx = idx & 127;
        g_Bt[b][idx] = __uint_as_float(f2tf32(at[kx * 132 + n] * rinv[kx]));
    }
}

// ---------------- 4) fused: stat finalize + GEMM1 operand prep ----------------
__global__ void prep2(const float* __restrict__ ffw, const float* __restrict__ ffb,
                      const float* __restrict__ gamma, const float* __restrict__ beta) {
    __shared__ float ssh[Fn], ssc[Fn];
    const int b = blockIdx.x, g = threadIdx.x;
    float s = 0.f, q = 0.f;
    #pragma unroll
    for (int t = 0; t < GRIDX; t++) {
        s += g_stat[b][t][0][g];
        q += g_stat[b][t][1][g];
    }
    const float inv = 1.f / (float)Ln;
    float m = s * inv;
    float v = q * inv - m * m;
    float rs = rsqrtf(v + 1e-5f);
    float sc = rs * gamma[g];
    float sh = fmaf(-m, sc, beta[g]);
    g_sc[b][g] = sc;
    ssc[g] = sc; ssh[g] = sh;
    __syncthreads();
    float bias2 = ffb[g];
    #pragma unroll 4
    for (int k = 0; k < Fn; k++) bias2 = fmaf(ssh[k], ffw[g * Fn + k], bias2);
    g_rsh[b][g] = ssh[g] + bias2;
    for (int idx = g; idx < Fn * Fn; idx += 128)
        g_Bt2[b][idx] = __uint_as_float(f2tf32(ffw[idx] * ssc[idx & 127]));
}

// ---------------- 5) tf32 GEMM: direct-STG epilogue, reg stats ----------------
// out = (A @ B^T) + A*rsc + rsh ; MODE0: rsc=1, rsh=0
template <int MODE>
__global__ __launch_bounds__(512, 1)
void mma_gemm(const float* __restrict__ xin) {
    extern __shared__ float sm[];
    float* const Abuf[2] = { sm, sm + FO_A1 };
    float2* const Bp = (float2*)(sm + FO_B);
    float4* const red = (float4*)(sm + FO_RED);

    const int tid = threadIdx.x, lane = tid & 31, w = tid >> 5;
    const int gid = lane >> 2, tig = lane & 3;
    const int wm = w & 3, wn = w >> 2;
    const int b = blockIdx.y;

    const size_t base = ((size_t)b * Ln + (size_t)blockIdx.x * TILES_PER_CTA * TILE_L) * Fn;
    const float* Xin = (MODE == 0 ? xin : g_x2) + base;
    float* Xout = (MODE == 0 ? g_x2 : g_y3) + base;

    const uint32_t ab32[2] = { smem_u32(Abuf[0]), smem_u32(Abuf[1]) };

    // prologue: cp.async tile 0
    #pragma unroll
    for (int i = tid; i < 4096; i += 512)
        cp16(ab32[0] + ((i >> 5) * 132 + (i & 31) * 4) * 4, Xin + (size_t)i * 4);
    CP_COMMIT();

    // build fragment-packed B: Bp[((wn*4+ni)*16+ks)*32 + lane] = {B[n][k], B[n][k+4]}
    {
        const float* Bg = (MODE == 0) ? &g_Bt[b][0] : &g_Bt2[b][0];
        #pragma unroll
        for (int idx = tid; idx < 8192; idx += 512) {
            int n = idx >> 6, j = idx & 63;
            int ks = j >> 2, tg = j & 3;
            int k = ks * 8 + tg;
            int wnn = n >> 5, nii = (n >> 3) & 3, gg = n & 7;
            int dst = (((wnn * 4 + nii) * 16) + ks) * 32 + gg * 4 + tg;
            Bp[dst] = make_float2(Bg[n * 128 + k], Bg[n * 128 + k + 4]);
        }
    }

    // epilogue affine params
    float2 rsc2[4], rsh2[4];
    #pragma unroll
    for (int ni = 0; ni < 4; ni++) {
        if (MODE == 1) {
            int col = wn * 32 + ni * 8 + tig * 2;
            rsc2[ni] = *(const float2*)&g_sc[b][col];
            rsh2[ni] = *(const float2*)&g_rsh[b][col];
        } else {
            rsc2[ni] = make_float2(1.f, 1.f);
            rsh2[ni] = make_float2(0.f, 0.f);
        }
    }

    float2 st_s[4], st_q[4];
    #pragma unroll
    for (int ni = 0; ni < 4; ni++) {
        st_s[ni] = make_float2(0.f, 0.f);
        st_q[ni] = make_float2(0.f, 0.f);
    }

    for (int t = 0; t < TILES_PER_CTA; t++) {
        if (t + 1 < TILES_PER_CTA) {
            const float* src = Xin + (size_t)(t + 1) * TILE_L * Fn;
            #pragma unroll
            for (int i = tid; i < 4096; i += 512)
                cp16(ab32[(t + 1) & 1] + ((i >> 5) * 132 + (i & 31) * 4) * 4, src + (size_t)i * 4);
        }
        CP_COMMIT();
        CP_WAIT1();
        __syncthreads();

        float* const buf = Abuf[t & 1];

        float c[2][4][4];
        #pragma unroll
        for (int mi = 0; mi < 2; mi++)
            #pragma unroll
            for (int ni = 0; ni < 4; ni++)
                #pragma unroll
                for (int j = 0; j < 4; j++) c[mi][ni][j] = 0.f;

        #pragma unroll
        for (int ks = 0; ks < 16; ks++) {
            const int k0 = ks * 8;
            const float* Ar = buf + (wm * 32 + gid) * 132 + k0 + tig;
            uint32_t a[2][4];
            a[0][0] = f2tf32(Ar[0]);
            a[0][1] = f2tf32(Ar[8 * 132]);
            a[0][2] = f2tf32(Ar[4]);
            a[0][3] = f2tf32(Ar[8 * 132 + 4]);
            a[1][0] = f2tf32(Ar[16 * 132]);
            a[1][1] = f2tf32(Ar[24 * 132]);
            a[1][2] = f2tf32(Ar[16 * 132 + 4]);
            a[1][3] = f2tf32(Ar[24 * 132 + 4]);
            #pragma unroll
            for (int ni = 0; ni < 4; ni++) {
                float2 bv = Bp[((wn * 4 + ni) * 16 + ks) * 32 + lane];
                uint32_t b0 = __float_as_uint(bv.x), b1 = __float_as_uint(bv.y);
                MMA_TF32(c[0][ni], a[0], b0, b1);
                MMA_TF32(c[1][ni], a[1], b0, b1);
            }
        }

        // direct epilogue: residual from A smem, STG to gmem, stats in regs
        float* Yt = Xout + (size_t)t * TILE_L * Fn;
        #pragma unroll
        for (int mi = 0; mi < 2; mi++)
            #pragma unroll
            for (int ni = 0; ni < 4; ni++) {
                const int r0 = wm * 32 + mi * 16 + gid;
                const int col = wn * 32 + ni * 8 + tig * 2;
                float2 x0 = *(float2*)&buf[r0 * 132 + col];
                float2 x1 = *(float2*)&buf[(r0 + 8) * 132 + col];
                float2 o0, o1;
                o0.x = c[mi][ni][0] + fmaf(x0.x, rsc2[ni].x, rsh2[ni].x);
                o0.y = c[mi][ni][1] + fmaf(x0.y, rsc2[ni].y, rsh2[ni].y);
                o1.x = c[mi][ni][2] + fmaf(x1.x, rsc2[ni].x, rsh2[ni].x);
                o1.y = c[mi][ni][3] + fmaf(x1.y, rsc2[ni].y, rsh2[ni].y);
                *(float2*)&Yt[(size_t)r0 * Fn + col] = o0;
                *(float2*)&Yt[(size_t)(r0 + 8) * Fn + col] = o1;
                st_s[ni].x += o0.x + o1.x;
                st_s[ni].y += o0.y + o1.y;
                st_q[ni].x += fmaf(o0.x, o0.x, o1.x * o1.x);
                st_q[ni].y += fmaf(o0.y, o0.y, o1.y * o1.y);
            }
        __syncthreads();   // buf reads done before next prefetch overwrites
    }

    // stats: shfl-reduce over gid (lanes xor 4,8,16), then cross-warp via smem
    #pragma unroll
    for (int ni = 0; ni < 4; ni++) {
        #pragma unroll
        for (int off = 4; off < 32; off <<= 1) {
            st_s[ni].x += __shfl_xor_sync(0xFFFFFFFFu, st_s[ni].x, off);
            st_s[ni].y += __shfl_xor_sync(0xFFFFFFFFu, st_s[ni].y, off);
            st_q[ni].x += __shfl_xor_sync(0xFFFFFFFFu, st_q[ni].x, off);
            st_q[ni].y += __shfl_xor_sync(0xFFFFFFFFu, st_q[ni].y, off);
        }
        if (gid == 0)
            red[w * 16 + ni * 4 + tig] = make_float4(st_s[ni].x, st_s[ni].y, st_q[ni].x, st_q[ni].y);
    }
    __syncthreads();
    if (tid < 128) {
        const int f = tid;
        const int fwn = f >> 5, fni = (f >> 3) & 3, ftg = (f >> 1) & 3, xy = f & 1;
        float s = 0.f, q = 0.f;
        #pragma unroll
        for (int m = 0; m < 4; m++) {
            float4 v = red[(fwn * 4 + m) * 16 + fni * 4 + ftg];
            s += xy ? v.y : v.x;
            q += xy ? v.w : v.z;
        }
        g_stat[b][blockIdx.x][0][f] = s;
        g_stat[b][blockIdx.x][1][f] = q;
    }
}

// ---------------- 6) stats -> scale/shift (for final norm) ----------------
__global__ void stat_reduce(const float* __restrict__ gamma, const float* __restrict__ beta) {
    const int b = blockIdx.x, g = threadIdx.x;
    float s = 0.f, q = 0.f;
    #pragma unroll
    for (int t = 0; t < GRIDX; t++) {
        s += g_stat[b][t][0][g];
        q += g_stat[b][t][1][g];
    }
    const float inv = 1.f / (float)Ln;
    float m = s * inv;
    float v = q * inv - m * m;
    float rs = rsqrtf(v + 1e-5f);
    float sc = rs * gamma[g];
    g_sc[b][g] = sc;
    g_sh[b][g] = fmaf(-m, sc, beta[g]);
}

// ---------------- 7) final normalize ----------------
__global__ void final_kernel(float* __restrict__ out) {
    int i = blockIdx.x * blockDim.x + threadIdx.x;
    int b = i >> 17;
    int fq = i & 31;
    float4 v = ((const float4*)g_y3)[i];
    float4 s = ((const float4*)&g_sc[b][0])[fq];
    float4 h = ((const float4*)&g_sh[b][0])[fq];
    v.x = fmaf(v.x, s.x, h.x); v.y = fmaf(v.y, s.y, h.y);
    v.z = fmaf(v.z, s.z, h.z); v.w = fmaf(v.w, s.w, h.w);
    ((float4*)out)[i] = v;
}

// ---------------- launch ----------------
extern "C" void kernel_launch(void* const* d_in, const int* in_sizes, int n_in,
                              void* d_out, int out_size) {
    const float* x     = (const float*)d_in[0];
    const float* qw    = (const float*)d_in[1];
    const float* qb    = (const float*)d_in[2];
    const float* kw    = (const float*)d_in[3];
    const float* kb    = (const float*)d_in[4];
    const float* ffw   = (const float*)d_in[5];
    const float* ffb   = (const float*)d_in[6];
    const float* gamma = (const float*)d_in[7];
    const float* beta  = (const float*)d_in[8];
    float* out = (float*)d_out;

    cudaFuncSetAttribute((const void*)mma_gemm<0>,
                         cudaFuncAttributeMaxDynamicSharedMemorySize, GEMM_SMEM);
    cudaFuncSetAttribute((const void*)mma_gemm<1>,
                         cudaFuncAttributeMaxDynamicSharedMemorySize, GEMM_SMEM);
    cudaFuncSetAttribute((const void*)att_prep,
                         cudaFuncAttributeMaxDynamicSharedMemorySize, ATT_SMEM);

    coef_kernel<<<(Ln + 255) / 256, 256>>>(qw, qb, kw, kb);
    qk_partial<<<dim3(NSPLIT, Bn), 256>>>(x);
    att_prep<<<Bn, 128, ATT_SMEM>>>();
    mma_gemm<0><<<dim3(GRIDX, Bn), 512, GEMM_SMEM>>>(x);
    prep2<<<Bn, Fn>>>(ffw, ffb, gamma, beta);
    mma_gemm<1><<<dim3(GRIDX, Bn), 512, GEMM_SMEM>>>(x);
    stat_reduce<<<Bn, Fn>>>(gamma, beta);
    final_kernel<<<TOT / 4 / 256, 256>>>(out);
}